// round 13
// baseline (speedup 1.0000x reference)
#include <cuda_runtime.h>
#include <cuda_fp16.h>
#include <math.h>
#include <cstdint>

#define BATCH 4
#define SEQ   4096
#define CDIM  512
#define HD    64
#define MROWS (BATCH*SEQ)   // 16384
#define QROWS (BATCH*32*128)  // 16384
#define NPIECE 320
#define NCTA   128

// ---------------- scratch (device globals) ----------------------------------
__device__ __align__(16) __half g_q [MROWS * HD];   // pre-scaled by 0.125*log2(e)
__device__ __align__(16) __half g_k [MROWS * HD];   // [B][32 tiles][128][64] swizzled
__device__ __align__(16) __half g_vt[BATCH * HD * SEQ]; // [B][32 tiles][64][128] swizzled
__device__ __align__(16) __half g_wt[3 * HD * CDIM];    // [8 chunks][192][64] swizzled
__device__ float  g_opart[4 * QROWS * 64];
__device__ float  g_lpart[4 * QROWS];
__device__ int    g_flag[BATCH * 32];
__device__ int    g_wready, g_wdone;       // W-convert barrier (self-reset)
__device__ int    g_pready, g_pdone;       // proj->attn barrier (self-reset)
__device__ int    g_ticket;                // attn work queue (self-reset)

#define EXPC 0.18033688f    // 0.125 * log2(e)

// ---------------- helpers ----------------------------------------------------
__device__ __forceinline__ uint32_t smem_u32(const void* p) {
    uint32_t a;
    asm("{ .reg .u64 t; cvta.to.shared.u64 t, %1; cvt.u32.u64 %0, t; }"
        : "=r"(a) : "l"(p));
    return a;
}
__device__ __forceinline__ void cp16(uint32_t dst, const void* src) {
    asm volatile("cp.async.cg.shared.global [%0], [%1], 16;\n"
                 :: "r"(dst), "l"(src));
}
#define CP_COMMIT() asm volatile("cp.async.commit_group;" ::: "memory")
#define CP_WAIT0()  asm volatile("cp.async.wait_group 0;" ::: "memory")

#define MBAR_INIT(a, c) \
    asm volatile("mbarrier.init.shared.b64 [%0], %1;" :: "r"(a), "r"(c) : "memory")
__device__ __forceinline__ void mbar_expect(uint32_t mbar, uint32_t bytes) {
    asm volatile("mbarrier.arrive.expect_tx.shared.b64 _, [%0], %1;"
                 :: "r"(mbar), "r"(bytes) : "memory");
}
__device__ __forceinline__ void bulk_g2s(uint32_t dst, const void* src,
                                         uint32_t bytes, uint32_t mbar) {
    asm volatile("cp.async.bulk.shared::cluster.global.mbarrier::complete_tx::bytes "
                 "[%0], [%1], %2, [%3];"
                 :: "r"(dst), "l"(src), "r"(bytes), "r"(mbar) : "memory");
}
__device__ __forceinline__ void mbar_wait(uint32_t mbar, uint32_t parity) {
    uint32_t done;
    asm volatile("{\n\t.reg .pred p;\n\t"
                 "mbarrier.try_wait.parity.acquire.cta.shared::cta.b64 p, [%1], %2;\n\t"
                 "selp.b32 %0, 1, 0, p;\n\t}"
                 : "=r"(done) : "r"(mbar), "r"(parity) : "memory");
    if (!done) {
        asm volatile("{\n\t.reg .pred P1;\n\t"
                     "WL_%=:\n\t"
                     "mbarrier.try_wait.parity.acquire.cta.shared::cta.b64 P1, [%0], %1, 0x989680;\n\t"
                     "@P1 bra.uni WD_%=;\n\t"
                     "bra.uni WL_%=;\n\t"
                     "WD_%=:\n\t}"
                     :: "r"(mbar), "r"(parity) : "memory");
    }
}

__device__ __forceinline__ uint32_t ld32h(const __half* p) {
    return *(const uint32_t*)p;
}
__device__ __forceinline__ uint32_t packh2(float a, float b) {
    __half2 h = __floats2half2_rn(a, b);
    return *(uint32_t*)&h;
}
__device__ __forceinline__ uint32_t h2exp2(uint32_t x) {
    uint32_t r;
    asm("ex2.approx.f16x2 %0, %1;" : "=r"(r) : "r"(x));
    return r;
}
__device__ __forceinline__ void ldsm4(uint32_t& r0, uint32_t& r1,
                                      uint32_t& r2, uint32_t& r3, uint32_t addr) {
    asm volatile("ldmatrix.sync.aligned.m8n8.x4.shared.b16 {%0,%1,%2,%3}, [%4];"
                 : "=r"(r0), "=r"(r1), "=r"(r2), "=r"(r3) : "r"(addr));
}
__device__ __forceinline__ void mma16816(float* c, const uint32_t* a,
                                         uint32_t b0, uint32_t b1) {
    asm volatile("mma.sync.aligned.m16n8k16.row.col.f32.f16.f16.f32 "
                 "{%0,%1,%2,%3}, {%4,%5,%6,%7}, {%8,%9}, {%0,%1,%2,%3};"
                 : "+f"(c[0]), "+f"(c[1]), "+f"(c[2]), "+f"(c[3])
                 : "r"(a[0]), "r"(a[1]), "r"(a[2]), "r"(a[3]),
                   "r"(b0), "r"(b1));
}
__device__ __forceinline__ void mma16816h(uint32_t* c, const uint32_t* a,
                                          uint32_t b0, uint32_t b1) {
    asm volatile("mma.sync.aligned.m16n8k16.row.col.f16.f16.f16.f16 "
                 "{%0,%1}, {%2,%3,%4,%5}, {%6,%7}, {%0,%1};"
                 : "+r"(c[0]), "+r"(c[1])
                 : "r"(a[0]), "r"(a[1]), "r"(a[2]), "r"(a[3]),
                   "r"(b0), "r"(b1));
}

// ---------------- smem layout (union of both phases) -------------------------
#define GX_OFF 0u
#define GX_BUF 34816u
#define GW_OFF 69632u
#define GW_BUF 24576u
#define GMB_OFF 118784u
#define FUSED_SMEM 118816u

#define OFF_Q 0u            // attn: [128][72] halves (18432 B)
#define OFF_K 18432u        // attn: 2 x 16384
#define OFF_V 51200u        // attn: 2 x 16384
#define AMB_OFF 83968u      // attn mbarriers (distinct from GMB_OFF)

// ---------------- fused persistent kernel ------------------------------------
__global__ __launch_bounds__(256, 1) void fused_kernel(
    const float* __restrict__ x,
    const float* __restrict__ Wk,
    const float* __restrict__ Wq,
    const float* __restrict__ Wv,
    float* __restrict__ out)
{
    extern __shared__ __align__(16) char sm[];
    __shared__ int s_ticket, s_old;
    const uint32_t sb = smem_u32(sm);

    const int tid  = threadIdx.x;
    const int lane = tid & 31;
    const int w    = tid >> 5;
    const int g    = lane >> 2;
    const int r4   = lane & 3;

    // =========================================================================
    // PHASE A: projection (round-11 body, verbatim)
    // =========================================================================
    {
        const int m0 = blockIdx.x * 128;

        // -- A0: cooperative W convert --
        {
            const float* Ws[3] = {Wq, Wk, Wv};
            if (tid < 96) {
                int u   = blockIdx.x * 96 + tid;
                int n   = u & 63;
                int k16 = (u >> 6) & 7;
                int pc  = u >> 9;
                int p   = pc % 3, c = pc / 3;
                const float* W = Ws[p];
                __half h[8];
                #pragma unroll
                for (int j = 0; j < 8; j++)
                    h[j] = __float2half_rn(W[(size_t)(c * 64 + k16 * 8 + j) * HD + n]);
                size_t dst = (size_t)(c * 192 + p * 64 + n) * 64 + ((k16 ^ (n & 7)) * 8);
                *(uint4*)&g_wt[dst] = *(uint4*)h;
            }
            __syncthreads();
            if (tid == 0) {
                __threadfence();
                atomicAdd(&g_wready, 1);
                while (atomicAdd(&g_wready, 0) < NCTA) { }
                int old = atomicAdd(&g_wdone, 1);
                if (old == NCTA - 1) { g_wready = 0; g_wdone = 0; }
            }
            __syncthreads();
        }

        const uint32_t mb[2] = {sb + GMB_OFF, sb + GMB_OFF + 8};
        if (tid == 0) { MBAR_INIT(mb[0], 8); MBAR_INIT(mb[1], 8); }
        __syncthreads();

        float acc[24][4];
        #pragma unroll
        for (int i = 0; i < 24; i++)
            #pragma unroll
            for (int j = 0; j < 4; j++) acc[i][j] = 0.f;

        auto issue = [&](int c) {
            if (lane == 0) {
                int buf = c & 1;
                uint32_t m = mb[buf];
                uint32_t bytes = 4096 + (w == 0 ? 24576 : 0);
                mbar_expect(m, bytes);
                #pragma unroll
                for (int i = 0; i < 16; i++) {
                    int r = 16 * w + i;
                    bulk_g2s(sb + GX_OFF + buf * GX_BUF + r * 272,
                             x + (size_t)(m0 + r) * CDIM + c * 64, 256, m);
                }
                if (w == 0)
                    bulk_g2s(sb + GW_OFF + buf * GW_BUF,
                             g_wt + (size_t)c * 12288, 24576, m);
            }
        };

        issue(0);
        uint32_t ph[2] = {0, 0};

        for (int c = 0; c < 8; c++) {
            if (c < 7) issue(c + 1);
            int buf = c & 1;
            mbar_wait(mb[buf], ph[buf]);
            ph[buf] ^= 1;

            const float*  xs  = (const float*)(sm + GX_OFF + buf * GX_BUF);
            const __half* wsm = (const __half*)(sm + GW_OFF + buf * GW_BUF);

            #pragma unroll
            for (int k0 = 0; k0 < 4; k0++) {
                uint32_t a[4];
                const float* xr0 = xs + (16 * w + g) * 68 + 16 * k0 + 2 * r4;
                const float* xr8 = xr0 + 8 * 68;
                float2 v0 = *(const float2*)xr0;
                float2 v1 = *(const float2*)xr8;
                float2 v2 = *(const float2*)(xr0 + 8);
                float2 v3 = *(const float2*)(xr8 + 8);
                a[0] = packh2(v0.x, v0.y);
                a[1] = packh2(v1.x, v1.y);
                a[2] = packh2(v2.x, v2.y);
                a[3] = packh2(v3.x, v3.y);
                #pragma unroll
                for (int pb = 0; pb < 3; pb++)
                    #pragma unroll
                    for (int nb = 0; nb < 8; nb++) {
                        const __half* row = wsm + (pb * 64 + 8 * nb + g) * 64;
                        uint32_t b0 = ld32h(row + (((2 * k0)     ^ g) * 8 + 2 * r4));
                        uint32_t b1 = ld32h(row + (((2 * k0 + 1) ^ g) * 8 + 2 * r4));
                        mma16816(acc[pb * 8 + nb], a, b0, b1);
                    }
            }
            __syncthreads();
        }

        const int r0 = m0 + 16 * w + g;
        const int r1 = r0 + 8;
        const int bb = r0 >> 12;
        const int t0v = r0 & 4095, t1v = r1 & 4095;
        const int kt0 = t0v >> 7, rl0 = t0v & 127;
        const int kt1 = t1v >> 7, rl1 = t1v & 127;

        #pragma unroll
        for (int nb = 0; nb < 8; nb++) {
            int col = 8 * nb + 2 * r4;
            *(__half2*)&g_q[(size_t)r0 * HD + col] =
                __floats2half2_rn(acc[nb][0] * EXPC, acc[nb][1] * EXPC);
            *(__half2*)&g_q[(size_t)r1 * HD + col] =
                __floats2half2_rn(acc[nb][2] * EXPC, acc[nb][3] * EXPC);
            {
                size_t o0 = ((size_t)(bb * 32 + kt0) << 14) + rl0 * 128
                          + ((nb ^ (rl0 & 7)) * 16 + 4 * r4);
                size_t o1 = ((size_t)(bb * 32 + kt1) << 14) + rl1 * 128
                          + ((nb ^ (rl1 & 7)) * 16 + 4 * r4);
                *(__half2*)((char*)g_k + o0) = __floats2half2_rn(acc[8 + nb][0], acc[8 + nb][1]);
                *(__half2*)((char*)g_k + o1) = __floats2half2_rn(acc[8 + nb][2], acc[8 + nb][3]);
            }
            {
                int h0 = 8 * nb + 2 * r4;
                #pragma unroll
                for (int u = 0; u < 2; u++) {
                    int h = h0 + u;
                    int sw = 2 * (h & 7);
                    {
                        int c = (t0v & 127) >> 3, ii = t0v & 7;
                        size_t o = ((size_t)(bb * 32 + kt0) << 14) + (size_t)h * 256
                                 + ((c ^ sw) * 16 + ii * 2);
                        *(__half*)((char*)g_vt + o) = __float2half_rn(acc[16 + nb][u]);
                    }
                    {
                        int c = (t1v & 127) >> 3, ii = t1v & 7;
                        size_t o = ((size_t)(bb * 32 + kt1) << 14) + (size_t)h * 256
                                 + ((c ^ sw) * 16 + ii * 2);
                        *(__half*)((char*)g_vt + o) = __float2half_rn(acc[16 + nb][2 + u]);
                    }
                }
            }
        }
    }

    // ==== grid barrier: all proj outputs visible before any attn reads =======
    __syncthreads();
    if (tid == 0) {
        __threadfence();
        atomicAdd(&g_pready, 1);
        while (atomicAdd(&g_pready, 0) < NCTA) { }
        int old = atomicAdd(&g_pdone, 1);
        if (old == NCTA - 1) { g_pready = 0; g_pdone = 0; }
    }
    __syncthreads();

    // =========================================================================
    // PHASE B: attention work-stealing loop (round-9 body per piece)
    // =========================================================================
    const int gg   = lane >> 2;
    const int rg   = w >> 1;
    const int ch   = w & 1;
    const int base_r = 32 * rg;
    const int lrow = (lane & 7) + ((lane >> 3) & 1) * 8;
    const int s3   = lane & 7;
    const int hi   = lane >> 4;

    const uint32_t mb[2] = {sb + AMB_OFF, sb + AMB_OFF + 8};
    if (tid == 0) { MBAR_INIT(mb[0], 1); MBAR_INIT(mb[1], 1); }
    uint32_t ph[2] = {0, 0};   // persists across pieces (each expect matched by one wait)
    const uint32_t krow = sb + OFF_K + (ch * 64 + lrow) * 128;
    const uint32_t vrow = sb + OFF_V + lrow * 256;

    while (true) {
        __syncthreads();   // smem (Of/Q/K overlays) free; mbar inits visible
        if (tid == 0) s_ticket = atomicAdd(&g_ticket, 1);
        __syncthreads();
        const int ticket = s_ticket;
        if (ticket >= NPIECE) {
            if (tid == 0 && ticket == NPIECE + NCTA - 1) {
                __threadfence();
                g_ticket = 0;   // last claim in total order -> safe reset
            }
            break;
        }

        // decode piece (heavy-first)
        int b = ticket & 3;
        int r = ticket >> 2;
        int qb, s, deg;
        if (r < 32)      { qb = 31 - (r >> 2); s = r & 3; deg = 4; }
        else if (r < 56) { int r2 = r - 32; qb = 23 - r2 / 3; s = r2 % 3; deg = 3; }
        else if (r < 72) { int r2 = r - 56; qb = 15 - (r2 >> 1); s = r2 & 1; deg = 2; }
        else             { qb = 7 - (r - 72); s = 0; deg = 1; }
        const int ntl = qb + 1;
        const int t0 = s * ntl / deg;
        const int t1 = (s + 1) * ntl / deg;
        const bool split = (deg > 1);

        const __half* qp = g_q + ((size_t)b * SEQ + (size_t)qb * 128) * HD;
        const char* kgb = (const char*)g_k  + ((size_t)b << 19);
        const char* vgb = (const char*)g_vt + ((size_t)b << 19);

        // Q load
        #pragma unroll
        for (int it = 0; it < 4; it++) {
            int idx = tid + it * 256;
            int rr = idx >> 3, j = idx & 7;
            cp16(sb + OFF_Q + rr * 144 + j * 16, qp + (size_t)rr * HD + j * 8);
        }
        CP_COMMIT();

        if (tid == 0) {
            mbar_expect(mb[0], 32768);
            bulk_g2s(sb + OFF_K, kgb + ((size_t)t0 << 14), 16384, mb[0]);
            bulk_g2s(sb + OFF_V, vgb + ((size_t)t0 << 14), 16384, mb[0]);
        }
        CP_WAIT0();
        __syncthreads();

        uint32_t qfrag[2][4][4];
        {
            __half* Qs = (__half*)(sm + OFF_Q);
            #pragma unroll
            for (int m = 0; m < 2; m++)
                #pragma unroll
                for (int k0 = 0; k0 < 4; k0++) {
                    const __half* qr  = Qs + (base_r + 16 * m + gg) * 72 + 16 * k0;
                    const __half* qr8 = qr + 8 * 72;
                    qfrag[m][k0][0] = ld32h(qr  + 2 * r4);
                    qfrag[m][k0][1] = ld32h(qr8 + 2 * r4);
                    qfrag[m][k0][2] = ld32h(qr  + 2 * r4 + 8);
                    qfrag[m][k0][3] = ld32h(qr8 + 2 * r4 + 8);
                }
        }

        float oacc[2][8][4];
        #pragma unroll
        for (int m = 0; m < 2; m++)
            #pragma unroll
            for (int nb = 0; nb < 8; nb++)
                #pragma unroll
                for (int cc = 0; cc < 4; cc++) oacc[m][nb][cc] = 0.f;
        float lacc[2][4];
        #pragma unroll
        for (int m = 0; m < 2; m++)
            #pragma unroll
            for (int cc = 0; cc < 4; cc++) lacc[m][cc] = 0.f;

        const uint32_t onesb = (gg == 0) ? 0x3C003C00u : 0u;

        for (int t = t0; t < t1; t++) {
            int buf = (t - t0) & 1;
            mbar_wait(mb[buf], ph[buf]);
            ph[buf] ^= 1;

            if (t + 1 < t1 && tid == 0) {
                int nbuf = buf ^ 1;
                mbar_expect(mb[nbuf], 32768);
                bulk_g2s(sb + OFF_K + nbuf * 16384u, kgb + ((size_t)(t + 1) << 14),
                         16384, mb[nbuf]);
                bulk_g2s(sb + OFF_V + nbuf * 16384u, vgb + ((size_t)(t + 1) << 14),
                         16384, mb[nbuf]);
            }

            uint32_t sacc[2][8][2];
            #pragma unroll
            for (int m = 0; m < 2; m++)
                #pragma unroll
                for (int nb = 0; nb < 8; nb++) {
                    sacc[m][nb][0] = 0u; sacc[m][nb][1] = 0u;
                }

            #pragma unroll
            for (int k0 = 0; k0 < 4; k0++) {
                uint32_t kaddr = krow + buf * 16384u + ((((2 * k0 + hi) ^ s3)) << 4);
                #pragma unroll
                for (int j = 0; j < 4; j++) {
                    uint32_t b00, b01, b10, b11;
                    ldsm4(b00, b01, b10, b11, kaddr + j * 2048);
                    mma16816h(sacc[0][2*j],     qfrag[0][k0], b00, b10);
                    mma16816h(sacc[0][2*j + 1], qfrag[0][k0], b01, b11);
                    mma16816h(sacc[1][2*j],     qfrag[1][k0], b00, b10);
                    mma16816h(sacc[1][2*j + 1], qfrag[1][k0], b01, b11);
                }
            }

            uint32_t pf[2][4][4];
            #pragma unroll
            for (int m = 0; m < 2; m++)
                #pragma unroll
                for (int kc = 0; kc < 4; kc++) {
                    pf[m][kc][0] = h2exp2(sacc[m][2*kc][0]);
                    pf[m][kc][1] = h2exp2(sacc[m][2*kc][1]);
                    pf[m][kc][2] = h2exp2(sacc[m][2*kc+1][0]);
                    pf[m][kc][3] = h2exp2(sacc[m][2*kc+1][1]);
                }

            #pragma unroll
            for (int m = 0; m < 2; m++)
                #pragma unroll
                for (int kc = 0; kc < 4; kc++)
                    mma16816(lacc[m], pf[m][kc], onesb, onesb);

            #pragma unroll
            for (int kc = 0; kc < 4; kc++) {
                uint32_t vaddr = vrow + buf * 16384u
                               + ((((8 * ch + 2 * kc + hi) ^ (2 * s3))) << 4);
                #pragma unroll
                for (int j = 0; j < 4; j++) {
                    uint32_t v00, v01, v10, v11;
                    ldsm4(v00, v01, v10, v11, vaddr + j * 4096);
                    mma16816(oacc[0][2*j],     pf[0][kc], v00, v10);
                    mma16816(oacc[0][2*j + 1], pf[0][kc], v01, v11);
                    mma16816(oacc[1][2*j],     pf[1][kc], v00, v10);
                    mma16816(oacc[1][2*j + 1], pf[1][kc], v01, v11);
                }
            }

            __syncthreads();
        }

        // ---- epilogue ----
        float* Of = (float*)(sm);
        float* ls = (float*)(sm + 33792u);

        if (r4 == 0) {
            ls[ch * 128 + base_r + gg]      = lacc[0][0];
            ls[ch * 128 + base_r + gg + 8]  = lacc[0][2];
            ls[ch * 128 + base_r + gg + 16] = lacc[1][0];
            ls[ch * 128 + base_r + gg + 24] = lacc[1][2];
        }
        if (ch == 1) {
            #pragma unroll
            for (int m = 0; m < 2; m++)
                #pragma unroll
                for (int nb = 0; nb < 8; nb++) {
                    int ra = base_r + 16 * m + gg;
                    *(float2*)&Of[ra * 66 + 8 * nb + 2 * r4] =
                        make_float2(oacc[m][nb][0], oacc[m][nb][1]);
                    *(float2*)&Of[(ra + 8) * 66 + 8 * nb + 2 * r4] =
                        make_float2(oacc[m][nb][2], oacc[m][nb][3]);
                }
        }
        __syncthreads();

        const int pid = b * 32 + qb;
        if (ch == 0) {
            #pragma unroll
            for (int m = 0; m < 2; m++) {
                int ra = base_r + 16 * m + gg;
                int rb = ra + 8;
                float la = ls[ra] + ls[128 + ra];
                float lb = ls[rb] + ls[128 + rb];
                if (!split) {
                    float ia = 1.0f / la, ib = 1.0f / lb;
                    #pragma unroll
                    for (int nb = 0; nb < 8; nb++) {
                        int col = 8 * nb + 2 * r4;
                        float2 oa = *(float2*)&Of[ra * 66 + col];
                        float2 ob = *(float2*)&Of[rb * 66 + col];
                        float2 va = make_float2((oacc[m][nb][0] + oa.x) * ia,
                                                (oacc[m][nb][1] + oa.y) * ia);
                        float2 vb = make_float2((oacc[m][nb][2] + ob.x) * ib,
                                                (oacc[m][nb][3] + ob.y) * ib);
                        size_t ga  = ((size_t)b * SEQ + (size_t)qb * 128 + ra) * HD + col;
                        size_t gb2 = ((size_t)b * SEQ + (size_t)qb * 128 + rb) * HD + col;
                        *(float2*)&out[ga]  = va;
                        *(float2*)&out[gb2] = vb;
                    }
                } else {
                    int pra = pid * 128 + ra;
                    int prb = pra + 8;
                    #pragma unroll
                    for (int nb = 0; nb < 8; nb++) {
                        int col = 8 * nb + 2 * r4;
                        float2 oa = *(float2*)&Of[ra * 66 + col];
                        float2 ob = *(float2*)&Of[rb * 66 + col];
                        float2 va = make_float2(oacc[m][nb][0] + oa.x,
                                                oacc[m][nb][1] + oa.y);
                        float2 vb = make_float2(oacc[m][nb][2] + ob.x,
                                                oacc[m][nb][3] + ob.y);
                        *(float2*)&g_opart[((size_t)s * QROWS + pra) * 64 + col] = va;
                        *(float2*)&g_opart[((size_t)s * QROWS + prb) * 64 + col] = vb;
                    }
                    if (r4 == 0) {
                        g_lpart[s * QROWS + pra] = la;
                        g_lpart[s * QROWS + prb] = lb;
                    }
                }
            }
        }

        // ---- in-kernel merge: last of the deg pieces merges ----
        if (split) {
            __threadfence();
            __syncthreads();
            if (tid == 0) s_old = atomicAdd(&g_flag[pid], 1);
            __syncthreads();
            if (s_old == deg - 1) {
                __threadfence();
                int prow0 = pid * 128;
                #pragma unroll
                for (int it = 0; it < 8; it++) {
                    int idx = tid + it * 256;
                    int rr  = idx >> 4;
                    int c4 = (idx & 15) * 4;
                    int pr = prow0 + rr;
                    float l = 0.f;
                    float4 o = make_float4(0.f, 0.f, 0.f, 0.f);
                    for (int u = 0; u < deg; u++) {
                        l += g_lpart[u * QROWS + pr];
                        float4 a = *(const float4*)&g_opart[((size_t)u * QROWS + pr) * 64 + c4];
                        o.x += a.x; o.y += a.y; o.z += a.z; o.w += a.w;
                    }
                    float inv = 1.0f / l;
                    o.x *= inv; o.y *= inv; o.z *= inv; o.w *= inv;
                    *(float4*)&out[((size_t)b * SEQ + (size_t)qb * 128 + rr) * HD + c4] = o;
                }
                if (tid == 0) g_flag[pid] = 0;
            }
        }
    }
}

// ---------------- launch -----------------------------------------------------
extern "C" void kernel_launch(void* const* d_in, const int* in_sizes, int n_in,
                              void* d_out, int out_size)
{
    const float* x  = (const float*)d_in[0];
    const float* Wk = (const float*)d_in[1];
    const float* Wq = (const float*)d_in[2];
    const float* Wv = (const float*)d_in[3];
    float* out = (float*)d_out;

    cudaFuncSetAttribute(fused_kernel, cudaFuncAttributeMaxDynamicSharedMemorySize,
                         (int)FUSED_SMEM);
    fused_kernel<<<NCTA, 256, FUSED_SMEM>>>(x, Wk, Wq, Wv, out);
}

// round 14
// speedup vs baseline: 1.1875x; 1.1875x over previous
#include <cuda_runtime.h>
#include <cuda_fp16.h>
#include <math.h>
#include <cstdint>

#define BATCH 4
#define SEQ   4096
#define CDIM  512
#define HD    64
#define MROWS (BATCH*SEQ)   // 16384
#define QROWS (BATCH*32*128)  // 16384

// ---------------- scratch (device globals) ----------------------------------
__device__ __align__(16) __half g_q [MROWS * HD];   // pre-scaled by 0.125*log2(e)
__device__ __align__(16) __half g_k [MROWS * HD];   // [B][32 tiles][128][64] swizzled
__device__ __align__(16) __half g_vt[BATCH * HD * SEQ]; // [B][32 tiles][64][128] swizzled
__device__ __align__(16) __half g_wt[3 * HD * CDIM];    // [8 chunks][192][64] swizzled
__device__ float  g_opart[4 * QROWS * 64];
__device__ float  g_lpart[4 * QROWS];
__device__ int    g_flag[BATCH * 32];
__device__ int    g_wready;
__device__ int    g_wdone;

#define EXPC 0.18033688f    // 0.125 * log2(e)

// ---------------- helpers ----------------------------------------------------
__device__ __forceinline__ uint32_t smem_u32(const void* p) {
    uint32_t a;
    asm("{ .reg .u64 t; cvta.to.shared.u64 t, %1; cvt.u32.u64 %0, t; }"
        : "=r"(a) : "l"(p));
    return a;
}
__device__ __forceinline__ void cp16(uint32_t dst, const void* src) {
    asm volatile("cp.async.cg.shared.global [%0], [%1], 16;\n"
                 :: "r"(dst), "l"(src));
}
#define CP_COMMIT() asm volatile("cp.async.commit_group;" ::: "memory")
#define CP_WAIT0()  asm volatile("cp.async.wait_group 0;" ::: "memory")

#define MBAR_INIT(a, c) \
    asm volatile("mbarrier.init.shared.b64 [%0], %1;" :: "r"(a), "r"(c) : "memory")
__device__ __forceinline__ void mbar_expect(uint32_t mbar, uint32_t bytes) {
    asm volatile("mbarrier.arrive.expect_tx.shared.b64 _, [%0], %1;"
                 :: "r"(mbar), "r"(bytes) : "memory");
}
__device__ __forceinline__ void bulk_g2s(uint32_t dst, const void* src,
                                         uint32_t bytes, uint32_t mbar) {
    asm volatile("cp.async.bulk.shared::cluster.global.mbarrier::complete_tx::bytes "
                 "[%0], [%1], %2, [%3];"
                 :: "r"(dst), "l"(src), "r"(bytes), "r"(mbar) : "memory");
}
__device__ __forceinline__ void mbar_wait(uint32_t mbar, uint32_t parity) {
    uint32_t done;
    asm volatile("{\n\t.reg .pred p;\n\t"
                 "mbarrier.try_wait.parity.acquire.cta.shared::cta.b64 p, [%1], %2;\n\t"
                 "selp.b32 %0, 1, 0, p;\n\t}"
                 : "=r"(done) : "r"(mbar), "r"(parity) : "memory");
    if (!done) {
        asm volatile("{\n\t.reg .pred P1;\n\t"
                     "WL_%=:\n\t"
                     "mbarrier.try_wait.parity.acquire.cta.shared::cta.b64 P1, [%0], %1, 0x989680;\n\t"
                     "@P1 bra.uni WD_%=;\n\t"
                     "bra.uni WL_%=;\n\t"
                     "WD_%=:\n\t}"
                     :: "r"(mbar), "r"(parity) : "memory");
    }
}

__device__ __forceinline__ uint32_t ld32h(const __half* p) {
    return *(const uint32_t*)p;
}
__device__ __forceinline__ uint32_t packh2(float a, float b) {
    __half2 h = __floats2half2_rn(a, b);
    return *(uint32_t*)&h;
}
__device__ __forceinline__ uint32_t h2exp2(uint32_t x) {
    uint32_t r;
    asm("ex2.approx.f16x2 %0, %1;" : "=r"(r) : "r"(x));
    return r;
}
__device__ __forceinline__ void ldsm4(uint32_t& r0, uint32_t& r1,
                                      uint32_t& r2, uint32_t& r3, uint32_t addr) {
    asm volatile("ldmatrix.sync.aligned.m8n8.x4.shared.b16 {%0,%1,%2,%3}, [%4];"
                 : "=r"(r0), "=r"(r1), "=r"(r2), "=r"(r3) : "r"(addr));
}
__device__ __forceinline__ void mma16816(float* c, const uint32_t* a,
                                         uint32_t b0, uint32_t b1) {
    asm volatile("mma.sync.aligned.m16n8k16.row.col.f32.f16.f16.f32 "
                 "{%0,%1,%2,%3}, {%4,%5,%6,%7}, {%8,%9}, {%0,%1,%2,%3};"
                 : "+f"(c[0]), "+f"(c[1]), "+f"(c[2]), "+f"(c[3])
                 : "r"(a[0]), "r"(a[1]), "r"(a[2]), "r"(a[3]),
                   "r"(b0), "r"(b1));
}
// scalar-operand variant (lets P fragments live directly in sacc regs)
__device__ __forceinline__ void mma16816s(float* c, uint32_t a0, uint32_t a1,
                                          uint32_t a2, uint32_t a3,
                                          uint32_t b0, uint32_t b1) {
    asm volatile("mma.sync.aligned.m16n8k16.row.col.f32.f16.f16.f32 "
                 "{%0,%1,%2,%3}, {%4,%5,%6,%7}, {%8,%9}, {%0,%1,%2,%3};"
                 : "+f"(c[0]), "+f"(c[1]), "+f"(c[2]), "+f"(c[3])
                 : "r"(a0), "r"(a1), "r"(a2), "r"(a3), "r"(b0), "r"(b1));
}
__device__ __forceinline__ void mma16816h(uint32_t* c, const uint32_t* a,
                                          uint32_t b0, uint32_t b1) {
    asm volatile("mma.sync.aligned.m16n8k16.row.col.f16.f16.f16.f16 "
                 "{%0,%1}, {%2,%3,%4,%5}, {%6,%7}, {%0,%1};"
                 : "+r"(c[0]), "+r"(c[1])
                 : "r"(a[0]), "r"(a[1]), "r"(a[2]), "r"(a[3]),
                   "r"(b0), "r"(b1));
}

// ---------------- projection GEMM (in-kernel W convert + bulk staging) -------
#define GX_OFF 0u
#define GX_BUF 34816u       // 128*272
#define GW_OFF 69632u
#define GW_BUF 24576u
#define GMB_OFF 118784u
#define GEMM_SMEM 118816u

__global__ __launch_bounds__(256, 1) void proj_gemm(
    const float* __restrict__ x,
    const float* __restrict__ Wk,
    const float* __restrict__ Wq,
    const float* __restrict__ Wv)
{
    extern __shared__ __align__(16) char sm[];
    const uint32_t sb = smem_u32(sm);

    const int tid  = threadIdx.x;
    const int lane = tid & 31;
    const int w    = tid >> 5;
    const int g    = lane >> 2;
    const int r4   = lane & 3;
    const int m0   = blockIdx.x * 128;

    // ==== phase 0: cooperative W convert (grid=128 <= 148 SMs, wave-1 safe) ==
    {
        const float* Ws[3] = {Wq, Wk, Wv};
        if (tid < 96) {
            int u   = blockIdx.x * 96 + tid;
            int n   = u & 63;
            int k16 = (u >> 6) & 7;
            int pc  = u >> 9;
            int p   = pc % 3, c = pc / 3;
            const float* W = Ws[p];
            __half h[8];
            #pragma unroll
            for (int j = 0; j < 8; j++)
                h[j] = __float2half_rn(W[(size_t)(c * 64 + k16 * 8 + j) * HD + n]);
            size_t dst = (size_t)(c * 192 + p * 64 + n) * 64 + ((k16 ^ (n & 7)) * 8);
            *(uint4*)&g_wt[dst] = *(uint4*)h;
        }
        __syncthreads();
        if (tid == 0) {
            __threadfence();
            atomicAdd(&g_wready, 1);
            while (atomicAdd(&g_wready, 0) < 128) { }
            int old = atomicAdd(&g_wdone, 1);
            if (old == 127) { g_wready = 0; g_wdone = 0; }
        }
        __syncthreads();
    }

    const uint32_t mb[2] = {sb + GMB_OFF, sb + GMB_OFF + 8};

    if (tid == 0) { MBAR_INIT(mb[0], 8); MBAR_INIT(mb[1], 8); }
    __syncthreads();

    float acc[24][4];
    #pragma unroll
    for (int i = 0; i < 24; i++)
        #pragma unroll
        for (int j = 0; j < 4; j++) acc[i][j] = 0.f;

    auto issue = [&](int c) {
        if (lane == 0) {
            int buf = c & 1;
            uint32_t m = mb[buf];
            uint32_t bytes = 4096 + (w == 0 ? 24576 : 0);
            mbar_expect(m, bytes);
            #pragma unroll
            for (int i = 0; i < 16; i++) {
                int r = 16 * w + i;
                bulk_g2s(sb + GX_OFF + buf * GX_BUF + r * 272,
                         x + (size_t)(m0 + r) * CDIM + c * 64, 256, m);
            }
            if (w == 0)
                bulk_g2s(sb + GW_OFF + buf * GW_BUF,
                         g_wt + (size_t)c * 12288, 24576, m);
        }
    };

    issue(0);
    uint32_t ph[2] = {0, 0};

    for (int c = 0; c < 8; c++) {
        if (c < 7) issue(c + 1);
        int buf = c & 1;
        mbar_wait(mb[buf], ph[buf]);
        ph[buf] ^= 1;

        const float*  xs  = (const float*)(sm + GX_OFF + buf * GX_BUF);
        const __half* wsm = (const __half*)(sm + GW_OFF + buf * GW_BUF);

        #pragma unroll
        for (int k0 = 0; k0 < 4; k0++) {
            uint32_t a[4];
            const float* xr0 = xs + (16 * w + g) * 68 + 16 * k0 + 2 * r4;
            const float* xr8 = xr0 + 8 * 68;
            float2 v0 = *(const float2*)xr0;
            float2 v1 = *(const float2*)xr8;
            float2 v2 = *(const float2*)(xr0 + 8);
            float2 v3 = *(const float2*)(xr8 + 8);
            a[0] = packh2(v0.x, v0.y);
            a[1] = packh2(v1.x, v1.y);
            a[2] = packh2(v2.x, v2.y);
            a[3] = packh2(v3.x, v3.y);
            #pragma unroll
            for (int pb = 0; pb < 3; pb++)
                #pragma unroll
                for (int nb = 0; nb < 8; nb++) {
                    const __half* row = wsm + (pb * 64 + 8 * nb + g) * 64;
                    uint32_t b0 = ld32h(row + (((2 * k0)     ^ g) * 8 + 2 * r4));
                    uint32_t b1 = ld32h(row + (((2 * k0 + 1) ^ g) * 8 + 2 * r4));
                    mma16816(acc[pb * 8 + nb], a, b0, b1);
                }
        }
        __syncthreads();
    }

    const int r0 = m0 + 16 * w + g;
    const int r1 = r0 + 8;
    const int bb = r0 >> 12;
    const int t0v = r0 & 4095, t1v = r1 & 4095;
    const int kt0 = t0v >> 7, rl0 = t0v & 127;
    const int kt1 = t1v >> 7, rl1 = t1v & 127;

    #pragma unroll
    for (int nb = 0; nb < 8; nb++) {
        int col = 8 * nb + 2 * r4;
        *(__half2*)&g_q[(size_t)r0 * HD + col] =
            __floats2half2_rn(acc[nb][0] * EXPC, acc[nb][1] * EXPC);
        *(__half2*)&g_q[(size_t)r1 * HD + col] =
            __floats2half2_rn(acc[nb][2] * EXPC, acc[nb][3] * EXPC);

        {
            size_t o0 = ((size_t)(bb * 32 + kt0) << 14) + rl0 * 128
                      + ((nb ^ (rl0 & 7)) * 16 + 4 * r4);
            size_t o1 = ((size_t)(bb * 32 + kt1) << 14) + rl1 * 128
                      + ((nb ^ (rl1 & 7)) * 16 + 4 * r4);
            *(__half2*)((char*)g_k + o0) = __floats2half2_rn(acc[8 + nb][0], acc[8 + nb][1]);
            *(__half2*)((char*)g_k + o1) = __floats2half2_rn(acc[8 + nb][2], acc[8 + nb][3]);
        }
        {
            int h0 = 8 * nb + 2 * r4;
            #pragma unroll
            for (int u = 0; u < 2; u++) {
                int h = h0 + u;
                int sw = 2 * (h & 7);
                {
                    int c = (t0v & 127) >> 3, ii = t0v & 7;
                    size_t o = ((size_t)(bb * 32 + kt0) << 14) + (size_t)h * 256
                             + ((c ^ sw) * 16 + ii * 2);
                    *(__half*)((char*)g_vt + o) = __float2half_rn(acc[16 + nb][u]);
                }
                {
                    int c = (t1v & 127) >> 3, ii = t1v & 7;
                    size_t o = ((size_t)(bb * 32 + kt1) << 14) + (size_t)h * 256
                             + ((c ^ sw) * 16 + ii * 2);
                    *(__half*)((char*)g_vt + o) = __float2half_rn(acc[16 + nb][2 + u]);
                }
            }
        }
    }
}

// ---------------- attention (round-9/11 shape + 2 local tweaks) --------------
#define OFF_Q 0u            // [128][72] halves padded (18432 B)
#define OFF_K 18432u        // 2 x 16384 swizzled tiles
#define OFF_V 51200u        // 2 x 16384 swizzled tiles
#define AMB_OFF 83968u
#define ATT_SMEM 84096u

__global__ __launch_bounds__(256, 1) void attn_kernel(float* __restrict__ out)
{
    extern __shared__ __align__(16) char sm[];
    __shared__ int s_old;
    const uint32_t sb = smem_u32(sm);
    __half* Qs = (__half*)(sm + OFF_Q);

    const int tid  = threadIdx.x;
    const int lane = tid & 31;
    const int wid  = tid >> 5;
    const int gg   = lane >> 2;
    const int r4   = lane & 3;
    const int rg   = wid >> 1;
    const int ch   = wid & 1;
    const int base_r = 32 * rg;
    const int lrow = (lane & 7) + ((lane >> 3) & 1) * 8;
    const int s3   = lane & 7;
    const int hi   = lane >> 4;

    // decode: pieces of <=8 tiles, heavy-first
    int b = blockIdx.x & 3;
    int r = blockIdx.x >> 2;             // 0..79
    int qb, s, deg;
    if (r < 32)      { qb = 31 - (r >> 2); s = r & 3; deg = 4; }
    else if (r < 56) { int r2 = r - 32; qb = 23 - r2 / 3; s = r2 % 3; deg = 3; }
    else if (r < 72) { int r2 = r - 56; qb = 15 - (r2 >> 1); s = r2 & 1; deg = 2; }
    else             { qb = 7 - (r - 72); s = 0; deg = 1; }
    const int ntl = qb + 1;
    const int t0 = s * ntl / deg;
    const int t1 = (s + 1) * ntl / deg;
    const bool split = (deg > 1);

    const __half* qp = g_q + ((size_t)b * SEQ + (size_t)qb * 128) * HD;
    const char* kgb = (const char*)g_k  + ((size_t)b << 19);
    const char* vgb = (const char*)g_vt + ((size_t)b << 19);

    const uint32_t mb[2] = {sb + AMB_OFF, sb + AMB_OFF + 8};
    if (tid == 0) { MBAR_INIT(mb[0], 1); MBAR_INIT(mb[1], 1); }

    // Q (one-time)
    #pragma unroll
    for (int it = 0; it < 4; it++) {
        int idx = tid + it * 256;
        int rr = idx >> 3, j = idx & 7;
        cp16(sb + OFF_Q + rr * 144 + j * 16, qp + (size_t)rr * HD + j * 8);
    }
    CP_COMMIT();
    __syncthreads();

    if (tid == 0) {
        mbar_expect(mb[0], 32768);
        bulk_g2s(sb + OFF_K, kgb + ((size_t)t0 << 14), 16384, mb[0]);
        bulk_g2s(sb + OFF_V, vgb + ((size_t)t0 << 14), 16384, mb[0]);
    }
    CP_WAIT0();
    __syncthreads();

    // Q fragments (pre-scaled by EXPC)
    uint32_t qfrag[2][4][4];
    #pragma unroll
    for (int m = 0; m < 2; m++)
        #pragma unroll
        for (int k0 = 0; k0 < 4; k0++) {
            const __half* qr  = Qs + (base_r + 16 * m + gg) * 72 + 16 * k0;
            const __half* qr8 = qr + 8 * 72;
            qfrag[m][k0][0] = ld32h(qr  + 2 * r4);
            qfrag[m][k0][1] = ld32h(qr8 + 2 * r4);
            qfrag[m][k0][2] = ld32h(qr  + 2 * r4 + 8);
            qfrag[m][k0][3] = ld32h(qr8 + 2 * r4 + 8);
        }

    float oacc[2][8][4];
    #pragma unroll
    for (int m = 0; m < 2; m++)
        #pragma unroll
        for (int nb = 0; nb < 8; nb++)
            #pragma unroll
            for (int cc = 0; cc < 4; cc++) oacc[m][nb][cc] = 0.f;
    float lacc[2][4];
    #pragma unroll
    for (int m = 0; m < 2; m++)
        #pragma unroll
        for (int cc = 0; cc < 4; cc++) lacc[m][cc] = 0.f;

    const uint32_t onesb = (gg == 0) ? 0x3C003C00u : 0u;
    const uint32_t krow = sb + OFF_K + (ch * 64 + lrow) * 128;
    const uint32_t vrow = sb + OFF_V + lrow * 256;
    uint32_t ph[2] = {0, 0};

    for (int t = t0; t < t1; t++) {
        int buf = (t - t0) & 1;

        // tweak 1: issue t+1 prefetch BEFORE waiting on tile t (nbuf is free:
        // readers of it finished at iteration t-1's __syncthreads)
        if (t + 1 < t1 && tid == 0) {
            int nbuf = buf ^ 1;
            mbar_expect(mb[nbuf], 32768);
            bulk_g2s(sb + OFF_K + nbuf * 16384u, kgb + ((size_t)(t + 1) << 14),
                     16384, mb[nbuf]);
            bulk_g2s(sb + OFF_V + nbuf * 16384u, vgb + ((size_t)(t + 1) << 14),
                     16384, mb[nbuf]);
        }

        mbar_wait(mb[buf], ph[buf]);
        ph[buf] ^= 1;

        // ---- S = Q K^T in f16 accumulation ----
        uint32_t sacc[2][8][2];
        #pragma unroll
        for (int m = 0; m < 2; m++)
            #pragma unroll
            for (int nb = 0; nb < 8; nb++) {
                sacc[m][nb][0] = 0u; sacc[m][nb][1] = 0u;
            }

        #pragma unroll
        for (int k0 = 0; k0 < 4; k0++) {
            uint32_t kaddr = krow + buf * 16384u + ((((2 * k0 + hi) ^ s3)) << 4);
            #pragma unroll
            for (int j = 0; j < 4; j++) {
                uint32_t b00, b01, b10, b11;
                ldsm4(b00, b01, b10, b11, kaddr + j * 2048);
                mma16816h(sacc[0][2*j],     qfrag[0][k0], b00, b10);
                mma16816h(sacc[0][2*j + 1], qfrag[0][k0], b01, b11);
                mma16816h(sacc[1][2*j],     qfrag[1][k0], b00, b10);
                mma16816h(sacc[1][2*j + 1], qfrag[1][k0], b01, b11);
            }
        }

        // tweak 2: softmax IN PLACE — sacc becomes the P fragments
        #pragma unroll
        for (int m = 0; m < 2; m++)
            #pragma unroll
            for (int nb = 0; nb < 8; nb++) {
                sacc[m][nb][0] = h2exp2(sacc[m][nb][0]);
                sacc[m][nb][1] = h2exp2(sacc[m][nb][1]);
            }

        // ---- l += P @ ones ----
        #pragma unroll
        for (int m = 0; m < 2; m++)
            #pragma unroll
            for (int kc = 0; kc < 4; kc++)
                mma16816s(lacc[m],
                          sacc[m][2*kc][0], sacc[m][2*kc][1],
                          sacc[m][2*kc+1][0], sacc[m][2*kc+1][1],
                          onesb, onesb);

        // ---- O += P @ V^T ----
        #pragma unroll
        for (int kc = 0; kc < 4; kc++) {
            uint32_t vaddr = vrow + buf * 16384u
                           + ((((8 * ch + 2 * kc + hi) ^ (2 * s3))) << 4);
            #pragma unroll
            for (int j = 0; j < 4; j++) {
                uint32_t v00, v01, v10, v11;
                ldsm4(v00, v01, v10, v11, vaddr + j * 4096);
                mma16816s(oacc[0][2*j],
                          sacc[0][2*kc][0], sacc[0][2*kc][1],
                          sacc[0][2*kc+1][0], sacc[0][2*kc+1][1], v00, v10);
                mma16816s(oacc[0][2*j + 1],
                          sacc[0][2*kc][0], sacc[0][2*kc][1],
                          sacc[0][2*kc+1][0], sacc[0][2*kc+1][1], v01, v11);
                mma16816s(oacc[1][2*j],
                          sacc[1][2*kc][0], sacc[1][2*kc][1],
                          sacc[1][2*kc+1][0], sacc[1][2*kc+1][1], v00, v10);
                mma16816s(oacc[1][2*j + 1],
                          sacc[1][2*kc][0], sacc[1][2*kc][1],
                          sacc[1][2*kc+1][0], sacc[1][2*kc+1][1], v01, v11);
            }
        }

        __syncthreads();
    }

    // ---- epilogue ----
    float* Of = (float*)(sm);
    float* ls = (float*)(sm + 33792u);

    if (r4 == 0) {
        ls[ch * 128 + base_r + gg]      = lacc[0][0];
        ls[ch * 128 + base_r + gg + 8]  = lacc[0][2];
        ls[ch * 128 + base_r + gg + 16] = lacc[1][0];
        ls[ch * 128 + base_r + gg + 24] = lacc[1][2];
    }
    if (ch == 1) {
        #pragma unroll
        for (int m = 0; m < 2; m++)
            #pragma unroll
            for (int nb = 0; nb < 8; nb++) {
                int ra = base_r + 16 * m + gg;
                *(float2*)&Of[ra * 66 + 8 * nb + 2 * r4] =
                    make_float2(oacc[m][nb][0], oacc[m][nb][1]);
                *(float2*)&Of[(ra + 8) * 66 + 8 * nb + 2 * r4] =
                    make_float2(oacc[m][nb][2], oacc[m][nb][3]);
            }
    }
    __syncthreads();

    const int pid = b * 32 + qb;
    if (ch == 0) {
        #pragma unroll
        for (int m = 0; m < 2; m++) {
            int ra = base_r + 16 * m + gg;
            int rb = ra + 8;
            float la = ls[ra] + ls[128 + ra];
            float lb = ls[rb] + ls[128 + rb];
            if (!split) {
                float ia = 1.0f / la, ib = 1.0f / lb;
                #pragma unroll
                for (int nb = 0; nb < 8; nb++) {
                    int col = 8 * nb + 2 * r4;
                    float2 oa = *(float2*)&Of[ra * 66 + col];
                    float2 ob = *(float2*)&Of[rb * 66 + col];
                    float2 va = make_float2((oacc[m][nb][0] + oa.x) * ia,
                                            (oacc[m][nb][1] + oa.y) * ia);
                    float2 vb = make_float2((oacc[m][nb][2] + ob.x) * ib,
                                            (oacc[m][nb][3] + ob.y) * ib);
                    size_t ga  = ((size_t)b * SEQ + (size_t)qb * 128 + ra) * HD + col;
                    size_t gb2 = ((size_t)b * SEQ + (size_t)qb * 128 + rb) * HD + col;
                    *(float2*)&out[ga]  = va;
                    *(float2*)&out[gb2] = vb;
                }
            } else {
                int pra = pid * 128 + ra;
                int prb = pra + 8;
                #pragma unroll
                for (int nb = 0; nb < 8; nb++) {
                    int col = 8 * nb + 2 * r4;
                    float2 oa = *(float2*)&Of[ra * 66 + col];
                    float2 ob = *(float2*)&Of[rb * 66 + col];
                    float2 va = make_float2(oacc[m][nb][0] + oa.x,
                                            oacc[m][nb][1] + oa.y);
                    float2 vb = make_float2(oacc[m][nb][2] + ob.x,
                                            oacc[m][nb][3] + ob.y);
                    *(float2*)&g_opart[((size_t)s * QROWS + pra) * 64 + col] = va;
                    *(float2*)&g_opart[((size_t)s * QROWS + prb) * 64 + col] = vb;
                }
                if (r4 == 0) {
                    g_lpart[s * QROWS + pra] = la;
                    g_lpart[s * QROWS + prb] = lb;
                }
            }
        }
    }

    // ---- in-kernel merge: last of the deg pieces merges ----
    if (split) {
        __threadfence();
        __syncthreads();
        if (tid == 0) s_old = atomicAdd(&g_flag[pid], 1);
        __syncthreads();
        if (s_old == deg - 1) {
            __threadfence();
            int prow0 = pid * 128;
            #pragma unroll
            for (int it = 0; it < 8; it++) {
                int idx = tid + it * 256;
                int rr  = idx >> 4;
                int c4 = (idx & 15) * 4;
                int pr = prow0 + rr;
                float l = 0.f;
                float4 o = make_float4(0.f, 0.f, 0.f, 0.f);
                for (int u = 0; u < deg; u++) {
                    l += g_lpart[u * QROWS + pr];
                    float4 a = *(const float4*)&g_opart[((size_t)u * QROWS + pr) * 64 + c4];
                    o.x += a.x; o.y += a.y; o.z += a.z; o.w += a.w;
                }
                float inv = 1.0f / l;
                o.x *= inv; o.y *= inv; o.z *= inv; o.w *= inv;
                *(float4*)&out[((size_t)b * SEQ + (size_t)qb * 128 + rr) * HD + c4] = o;
            }
            if (tid == 0) g_flag[pid] = 0;
        }
    }
}

// ---------------- launch -----------------------------------------------------
extern "C" void kernel_launch(void* const* d_in, const int* in_sizes, int n_in,
                              void* d_out, int out_size)
{
    const float* x  = (const float*)d_in[0];
    const float* Wk = (const float*)d_in[1];
    const float* Wq = (const float*)d_in[2];
    const float* Wv = (const float*)d_in[3];
    float* out = (float*)d_out;

    cudaFuncSetAttribute(proj_gemm, cudaFuncAttributeMaxDynamicSharedMemorySize,
                         (int)GEMM_SMEM);
    proj_gemm<<<128, 256, GEMM_SMEM>>>(x, Wk, Wq, Wv);

    cudaFuncSetAttribute(attn_kernel, cudaFuncAttributeMaxDynamicSharedMemorySize,
                         (int)ATT_SMEM);
    attn_kernel<<<320, 256, ATT_SMEM>>>(out);
}

// round 15
// speedup vs baseline: 1.2169x; 1.0248x over previous
#include <cuda_runtime.h>
#include <cuda_fp16.h>
#include <math.h>
#include <cstdint>

#define BATCH 4
#define SEQ   4096
#define CDIM  512
#define HD    64
#define MROWS (BATCH*SEQ)   // 16384
#define QROWS (BATCH*32*128)  // 16384

// ---------------- scratch (device globals) ----------------------------------
__device__ __align__(16) __half g_q [MROWS * HD];   // pre-scaled by 0.125*log2(e)
__device__ __align__(16) __half g_k [MROWS * HD];   // [B][32 tiles][128][64] swizzled
__device__ __align__(16) __half g_vt[BATCH * HD * SEQ]; // [B][32 tiles][64][128] swizzled
__device__ __align__(16) __half g_wt[3 * HD * CDIM];    // [8 chunks][192][64] swizzled
__device__ float  g_opart[4 * QROWS * 64];
__device__ float  g_lpart[4 * QROWS];
__device__ int    g_flag[BATCH * 32];
__device__ int    g_wready;
__device__ int    g_wdone;

#define EXPC 0.18033688f    // 0.125 * log2(e)

// ---------------- helpers ----------------------------------------------------
__device__ __forceinline__ uint32_t smem_u32(const void* p) {
    uint32_t a;
    asm("{ .reg .u64 t; cvta.to.shared.u64 t, %1; cvt.u32.u64 %0, t; }"
        : "=r"(a) : "l"(p));
    return a;
}
__device__ __forceinline__ void cp16(uint32_t dst, const void* src) {
    asm volatile("cp.async.cg.shared.global [%0], [%1], 16;\n"
                 :: "r"(dst), "l"(src));
}
#define CP_COMMIT() asm volatile("cp.async.commit_group;" ::: "memory")
#define CP_WAIT0()  asm volatile("cp.async.wait_group 0;" ::: "memory")

#define MBAR_INIT(a, c) \
    asm volatile("mbarrier.init.shared.b64 [%0], %1;" :: "r"(a), "r"(c) : "memory")
__device__ __forceinline__ void mbar_expect(uint32_t mbar, uint32_t bytes) {
    asm volatile("mbarrier.arrive.expect_tx.shared.b64 _, [%0], %1;"
                 :: "r"(mbar), "r"(bytes) : "memory");
}
__device__ __forceinline__ void bulk_g2s(uint32_t dst, const void* src,
                                         uint32_t bytes, uint32_t mbar) {
    asm volatile("cp.async.bulk.shared::cluster.global.mbarrier::complete_tx::bytes "
                 "[%0], [%1], %2, [%3];"
                 :: "r"(dst), "l"(src), "r"(bytes), "r"(mbar) : "memory");
}
__device__ __forceinline__ void mbar_wait(uint32_t mbar, uint32_t parity) {
    uint32_t done;
    asm volatile("{\n\t.reg .pred p;\n\t"
                 "mbarrier.try_wait.parity.acquire.cta.shared::cta.b64 p, [%1], %2;\n\t"
                 "selp.b32 %0, 1, 0, p;\n\t}"
                 : "=r"(done) : "r"(mbar), "r"(parity) : "memory");
    if (!done) {
        asm volatile("{\n\t.reg .pred P1;\n\t"
                     "WL_%=:\n\t"
                     "mbarrier.try_wait.parity.acquire.cta.shared::cta.b64 P1, [%0], %1, 0x989680;\n\t"
                     "@P1 bra.uni WD_%=;\n\t"
                     "bra.uni WL_%=;\n\t"
                     "WD_%=:\n\t}"
                     :: "r"(mbar), "r"(parity) : "memory");
    }
}

__device__ __forceinline__ uint32_t ld32h(const __half* p) {
    return *(const uint32_t*)p;
}
__device__ __forceinline__ uint32_t packh2(float a, float b) {
    __half2 h = __floats2half2_rn(a, b);
    return *(uint32_t*)&h;
}
__device__ __forceinline__ uint32_t h2exp2(uint32_t x) {
    uint32_t r;
    asm("ex2.approx.f16x2 %0, %1;" : "=r"(r) : "r"(x));
    return r;
}
__device__ __forceinline__ void ldsm4(uint32_t& r0, uint32_t& r1,
                                      uint32_t& r2, uint32_t& r3, uint32_t addr) {
    asm volatile("ldmatrix.sync.aligned.m8n8.x4.shared.b16 {%0,%1,%2,%3}, [%4];"
                 : "=r"(r0), "=r"(r1), "=r"(r2), "=r"(r3) : "r"(addr));
}
__device__ __forceinline__ void mma16816(float* c, const uint32_t* a,
                                         uint32_t b0, uint32_t b1) {
    asm volatile("mma.sync.aligned.m16n8k16.row.col.f32.f16.f16.f32 "
                 "{%0,%1,%2,%3}, {%4,%5,%6,%7}, {%8,%9}, {%0,%1,%2,%3};"
                 : "+f"(c[0]), "+f"(c[1]), "+f"(c[2]), "+f"(c[3])
                 : "r"(a[0]), "r"(a[1]), "r"(a[2]), "r"(a[3]),
                   "r"(b0), "r"(b1));
}
// scalar-operand f32-acc variant
__device__ __forceinline__ void mma16816s(float* c, uint32_t a0, uint32_t a1,
                                          uint32_t a2, uint32_t a3,
                                          uint32_t b0, uint32_t b1) {
    asm volatile("mma.sync.aligned.m16n8k16.row.col.f32.f16.f16.f32 "
                 "{%0,%1,%2,%3}, {%4,%5,%6,%7}, {%8,%9}, {%0,%1,%2,%3};"
                 : "+f"(c[0]), "+f"(c[1]), "+f"(c[2]), "+f"(c[3])
                 : "r"(a0), "r"(a1), "r"(a2), "r"(a3), "r"(b0), "r"(b1));
}
// f16-acc, array A
__device__ __forceinline__ void mma16816h(uint32_t* c, const uint32_t* a,
                                          uint32_t b0, uint32_t b1) {
    asm volatile("mma.sync.aligned.m16n8k16.row.col.f16.f16.f16.f16 "
                 "{%0,%1}, {%2,%3,%4,%5}, {%6,%7}, {%0,%1};"
                 : "+r"(c[0]), "+r"(c[1])
                 : "r"(a[0]), "r"(a[1]), "r"(a[2]), "r"(a[3]),
                   "r"(b0), "r"(b1));
}
// f16-acc, scalar A operands (P lives in sacc regs)
__device__ __forceinline__ void mma16816hs(uint32_t* c, uint32_t a0, uint32_t a1,
                                           uint32_t a2, uint32_t a3,
                                           uint32_t b0, uint32_t b1) {
    asm volatile("mma.sync.aligned.m16n8k16.row.col.f16.f16.f16.f16 "
                 "{%0,%1}, {%2,%3,%4,%5}, {%6,%7}, {%0,%1};"
                 : "+r"(c[0]), "+r"(c[1])
                 : "r"(a0), "r"(a1), "r"(a2), "r"(a3), "r"(b0), "r"(b1));
}

// ---------------- projection GEMM (in-kernel W convert + bulk staging) -------
#define GX_OFF 0u
#define GX_BUF 34816u       // 128*272
#define GW_OFF 69632u
#define GW_BUF 24576u
#define GMB_OFF 118784u
#define GEMM_SMEM 118816u

__global__ __launch_bounds__(256, 1) void proj_gemm(
    const float* __restrict__ x,
    const float* __restrict__ Wk,
    const float* __restrict__ Wq,
    const float* __restrict__ Wv)
{
    extern __shared__ __align__(16) char sm[];
    const uint32_t sb = smem_u32(sm);

    const int tid  = threadIdx.x;
    const int lane = tid & 31;
    const int w    = tid >> 5;
    const int g    = lane >> 2;
    const int r4   = lane & 3;
    const int m0   = blockIdx.x * 128;

    // ==== phase 0: cooperative W convert (grid=128 <= 148 SMs, wave-1 safe) ==
    {
        const float* Ws[3] = {Wq, Wk, Wv};
        if (tid < 96) {
            int u   = blockIdx.x * 96 + tid;
            int n   = u & 63;
            int k16 = (u >> 6) & 7;
            int pc  = u >> 9;
            int p   = pc % 3, c = pc / 3;
            const float* W = Ws[p];
            __half h[8];
            #pragma unroll
            for (int j = 0; j < 8; j++)
                h[j] = __float2half_rn(W[(size_t)(c * 64 + k16 * 8 + j) * HD + n]);
            size_t dst = (size_t)(c * 192 + p * 64 + n) * 64 + ((k16 ^ (n & 7)) * 8);
            *(uint4*)&g_wt[dst] = *(uint4*)h;
        }
        __syncthreads();
        if (tid == 0) {
            __threadfence();
            atomicAdd(&g_wready, 1);
            while (atomicAdd(&g_wready, 0) < 128) { }
            int old = atomicAdd(&g_wdone, 1);
            if (old == 127) { g_wready = 0; g_wdone = 0; }
        }
        __syncthreads();
    }

    const uint32_t mb[2] = {sb + GMB_OFF, sb + GMB_OFF + 8};

    if (tid == 0) { MBAR_INIT(mb[0], 8); MBAR_INIT(mb[1], 8); }
    __syncthreads();

    float acc[24][4];
    #pragma unroll
    for (int i = 0; i < 24; i++)
        #pragma unroll
        for (int j = 0; j < 4; j++) acc[i][j] = 0.f;

    auto issue = [&](int c) {
        if (lane == 0) {
            int buf = c & 1;
            uint32_t m = mb[buf];
            uint32_t bytes = 4096 + (w == 0 ? 24576 : 0);
            mbar_expect(m, bytes);
            #pragma unroll
            for (int i = 0; i < 16; i++) {
                int r = 16 * w + i;
                bulk_g2s(sb + GX_OFF + buf * GX_BUF + r * 272,
                         x + (size_t)(m0 + r) * CDIM + c * 64, 256, m);
            }
            if (w == 0)
                bulk_g2s(sb + GW_OFF + buf * GW_BUF,
                         g_wt + (size_t)c * 12288, 24576, m);
        }
    };

    issue(0);
    uint32_t ph[2] = {0, 0};

    for (int c = 0; c < 8; c++) {
        if (c < 7) issue(c + 1);
        int buf = c & 1;
        mbar_wait(mb[buf], ph[buf]);
        ph[buf] ^= 1;

        const float*  xs  = (const float*)(sm + GX_OFF + buf * GX_BUF);
        const __half* wsm = (const __half*)(sm + GW_OFF + buf * GW_BUF);

        #pragma unroll
        for (int k0 = 0; k0 < 4; k0++) {
            uint32_t a[4];
            const float* xr0 = xs + (16 * w + g) * 68 + 16 * k0 + 2 * r4;
            const float* xr8 = xr0 + 8 * 68;
            float2 v0 = *(const float2*)xr0;
            float2 v1 = *(const float2*)xr8;
            float2 v2 = *(const float2*)(xr0 + 8);
            float2 v3 = *(const float2*)(xr8 + 8);
            a[0] = packh2(v0.x, v0.y);
            a[1] = packh2(v1.x, v1.y);
            a[2] = packh2(v2.x, v2.y);
            a[3] = packh2(v3.x, v3.y);
            #pragma unroll
            for (int pb = 0; pb < 3; pb++)
                #pragma unroll
                for (int nb = 0; nb < 8; nb++) {
                    const __half* row = wsm + (pb * 64 + 8 * nb + g) * 64;
                    uint32_t b0 = ld32h(row + (((2 * k0)     ^ g) * 8 + 2 * r4));
                    uint32_t b1 = ld32h(row + (((2 * k0 + 1) ^ g) * 8 + 2 * r4));
                    mma16816(acc[pb * 8 + nb], a, b0, b1);
                }
        }
        __syncthreads();
    }

    const int r0 = m0 + 16 * w + g;
    const int r1 = r0 + 8;
    const int bb = r0 >> 12;
    const int t0v = r0 & 4095, t1v = r1 & 4095;
    const int kt0 = t0v >> 7, rl0 = t0v & 127;
    const int kt1 = t1v >> 7, rl1 = t1v & 127;

    #pragma unroll
    for (int nb = 0; nb < 8; nb++) {
        int col = 8 * nb + 2 * r4;
        *(__half2*)&g_q[(size_t)r0 * HD + col] =
            __floats2half2_rn(acc[nb][0] * EXPC, acc[nb][1] * EXPC);
        *(__half2*)&g_q[(size_t)r1 * HD + col] =
            __floats2half2_rn(acc[nb][2] * EXPC, acc[nb][3] * EXPC);

        {
            size_t o0 = ((size_t)(bb * 32 + kt0) << 14) + rl0 * 128
                      + ((nb ^ (rl0 & 7)) * 16 + 4 * r4);
            size_t o1 = ((size_t)(bb * 32 + kt1) << 14) + rl1 * 128
                      + ((nb ^ (rl1 & 7)) * 16 + 4 * r4);
            *(__half2*)((char*)g_k + o0) = __floats2half2_rn(acc[8 + nb][0], acc[8 + nb][1]);
            *(__half2*)((char*)g_k + o1) = __floats2half2_rn(acc[8 + nb][2], acc[8 + nb][3]);
        }
        {
            int h0 = 8 * nb + 2 * r4;
            #pragma unroll
            for (int u = 0; u < 2; u++) {
                int h = h0 + u;
                int sw = 2 * (h & 7);
                {
                    int c = (t0v & 127) >> 3, ii = t0v & 7;
                    size_t o = ((size_t)(bb * 32 + kt0) << 14) + (size_t)h * 256
                             + ((c ^ sw) * 16 + ii * 2);
                    *(__half*)((char*)g_vt + o) = __float2half_rn(acc[16 + nb][u]);
                }
                {
                    int c = (t1v & 127) >> 3, ii = t1v & 7;
                    size_t o = ((size_t)(bb * 32 + kt1) << 14) + (size_t)h * 256
                             + ((c ^ sw) * 16 + ii * 2);
                    *(__half*)((char*)g_vt + o) = __float2half_rn(acc[16 + nb][2 + u]);
                }
            }
        }
    }
}

// ---------------- attention: 2 CTAs/SM (<=128 regs), f16 O accumulation ------
#define OFF_Q 0u            // [128][72] halves padded (18432 B)
#define OFF_K 18432u        // 2 x 16384 swizzled tiles
#define OFF_V 51200u        // 2 x 16384 swizzled tiles
#define AMB_OFF 83968u
#define ATT_SMEM 84096u

__global__ __launch_bounds__(256, 2) void attn_kernel(float* __restrict__ out)
{
    extern __shared__ __align__(16) char sm[];
    __shared__ int s_old;
    const uint32_t sb = smem_u32(sm);
    __half* Qs = (__half*)(sm + OFF_Q);

    const int tid  = threadIdx.x;
    const int lane = tid & 31;
    const int wid  = tid >> 5;
    const int gg   = lane >> 2;
    const int r4   = lane & 3;
    const int rg   = wid >> 1;
    const int ch   = wid & 1;
    const int base_r = 32 * rg;
    const int lrow = (lane & 7) + ((lane >> 3) & 1) * 8;
    const int s3   = lane & 7;
    const int hi   = lane >> 4;

    // decode: pieces of <=8 tiles, heavy-first
    int b = blockIdx.x & 3;
    int r = blockIdx.x >> 2;             // 0..79
    int qb, s, deg;
    if (r < 32)      { qb = 31 - (r >> 2); s = r & 3; deg = 4; }
    else if (r < 56) { int r2 = r - 32; qb = 23 - r2 / 3; s = r2 % 3; deg = 3; }
    else if (r < 72) { int r2 = r - 56; qb = 15 - (r2 >> 1); s = r2 & 1; deg = 2; }
    else             { qb = 7 - (r - 72); s = 0; deg = 1; }
    const int ntl = qb + 1;
    const int t0 = s * ntl / deg;
    const int t1 = (s + 1) * ntl / deg;
    const bool split = (deg > 1);

    const __half* qp = g_q + ((size_t)b * SEQ + (size_t)qb * 128) * HD;
    const char* kgb = (const char*)g_k  + ((size_t)b << 19);
    const char* vgb = (const char*)g_vt + ((size_t)b << 19);

    const uint32_t mb[2] = {sb + AMB_OFF, sb + AMB_OFF + 8};
    if (tid == 0) { MBAR_INIT(mb[0], 1); MBAR_INIT(mb[1], 1); }

    // Q (one-time)
    #pragma unroll
    for (int it = 0; it < 4; it++) {
        int idx = tid + it * 256;
        int rr = idx >> 3, j = idx & 7;
        cp16(sb + OFF_Q + rr * 144 + j * 16, qp + (size_t)rr * HD + j * 8);
    }
    CP_COMMIT();
    __syncthreads();

    if (tid == 0) {
        mbar_expect(mb[0], 32768);
        bulk_g2s(sb + OFF_K, kgb + ((size_t)t0 << 14), 16384, mb[0]);
        bulk_g2s(sb + OFF_V, vgb + ((size_t)t0 << 14), 16384, mb[0]);
    }
    CP_WAIT0();
    __syncthreads();

    // Q fragments (pre-scaled by EXPC)
    uint32_t qfrag[2][4][4];
    #pragma unroll
    for (int m = 0; m < 2; m++)
        #pragma unroll
        for (int k0 = 0; k0 < 4; k0++) {
            const __half* qr  = Qs + (base_r + 16 * m + gg) * 72 + 16 * k0;
            const __half* qr8 = qr + 8 * 72;
            qfrag[m][k0][0] = ld32h(qr  + 2 * r4);
            qfrag[m][k0][1] = ld32h(qr8 + 2 * r4);
            qfrag[m][k0][2] = ld32h(qr  + 2 * r4 + 8);
            qfrag[m][k0][3] = ld32h(qr8 + 2 * r4 + 8);
        }

    // O accumulators in f16x2 (2 regs per m16n8 tile)
    uint32_t oacc[2][8][2];
    #pragma unroll
    for (int m = 0; m < 2; m++)
        #pragma unroll
        for (int nb = 0; nb < 8; nb++) { oacc[m][nb][0] = 0u; oacc[m][nb][1] = 0u; }
    float lacc[2][4];
    #pragma unroll
    for (int m = 0; m < 2; m++)
        #pragma unroll
        for (int cc = 0; cc < 4; cc++) lacc[m][cc] = 0.f;

    const uint32_t onesb = (gg == 0) ? 0x3C003C00u : 0u;
    const uint32_t krow = sb + OFF_K + (ch * 64 + lrow) * 128;
    const uint32_t vrow = sb + OFF_V + lrow * 256;
    uint32_t ph[2] = {0, 0};

    for (int t = t0; t < t1; t++) {
        int buf = (t - t0) & 1;

        // prefetch t+1 before waiting on t (target buffer free since t-1's sync)
        if (t + 1 < t1 && tid == 0) {
            int nbuf = buf ^ 1;
            mbar_expect(mb[nbuf], 32768);
            bulk_g2s(sb + OFF_K + nbuf * 16384u, kgb + ((size_t)(t + 1) << 14),
                     16384, mb[nbuf]);
            bulk_g2s(sb + OFF_V + nbuf * 16384u, vgb + ((size_t)(t + 1) << 14),
                     16384, mb[nbuf]);
        }

        mbar_wait(mb[buf], ph[buf]);
        ph[buf] ^= 1;

        // ---- S = Q K^T in f16 accumulation ----
        uint32_t sacc[2][8][2];
        #pragma unroll
        for (int m = 0; m < 2; m++)
            #pragma unroll
            for (int nb = 0; nb < 8; nb++) {
                sacc[m][nb][0] = 0u; sacc[m][nb][1] = 0u;
            }

        #pragma unroll
        for (int k0 = 0; k0 < 4; k0++) {
            uint32_t kaddr = krow + buf * 16384u + ((((2 * k0 + hi) ^ s3)) << 4);
            #pragma unroll
            for (int j = 0; j < 4; j++) {
                uint32_t b00, b01, b10, b11;
                ldsm4(b00, b01, b10, b11, kaddr + j * 2048);
                mma16816h(sacc[0][2*j],     qfrag[0][k0], b00, b10);
                mma16816h(sacc[0][2*j + 1], qfrag[0][k0], b01, b11);
                mma16816h(sacc[1][2*j],     qfrag[1][k0], b00, b10);
                mma16816h(sacc[1][2*j + 1], qfrag[1][k0], b01, b11);
            }
        }

        // ---- softmax in place: sacc becomes P fragments ----
        #pragma unroll
        for (int m = 0; m < 2; m++)
            #pragma unroll
            for (int nb = 0; nb < 8; nb++) {
                sacc[m][nb][0] = h2exp2(sacc[m][nb][0]);
                sacc[m][nb][1] = h2exp2(sacc[m][nb][1]);
            }

        // ---- l += P @ ones (f32 acc, precision-critical) ----
        #pragma unroll
        for (int m = 0; m < 2; m++)
            #pragma unroll
            for (int kc = 0; kc < 4; kc++)
                mma16816s(lacc[m],
                          sacc[m][2*kc][0], sacc[m][2*kc][1],
                          sacc[m][2*kc+1][0], sacc[m][2*kc+1][1],
                          onesb, onesb);

        // ---- O += P @ V^T (f16 acc) ----
        #pragma unroll
        for (int kc = 0; kc < 4; kc++) {
            uint32_t vaddr = vrow + buf * 16384u
                           + ((((8 * ch + 2 * kc + hi) ^ (2 * s3))) << 4);
            #pragma unroll
            for (int j = 0; j < 4; j++) {
                uint32_t v00, v01, v10, v11;
                ldsm4(v00, v01, v10, v11, vaddr + j * 4096);
                mma16816hs(oacc[0][2*j],
                           sacc[0][2*kc][0], sacc[0][2*kc][1],
                           sacc[0][2*kc+1][0], sacc[0][2*kc+1][1], v00, v10);
                mma16816hs(oacc[0][2*j + 1],
                           sacc[0][2*kc][0], sacc[0][2*kc][1],
                           sacc[0][2*kc+1][0], sacc[0][2*kc+1][1], v01, v11);
                mma16816hs(oacc[1][2*j],
                           sacc[1][2*kc][0], sacc[1][2*kc][1],
                           sacc[1][2*kc+1][0], sacc[1][2*kc+1][1], v00, v10);
                mma16816hs(oacc[1][2*j + 1],
                           sacc[1][2*kc][0], sacc[1][2*kc][1],
                           sacc[1][2*kc+1][0], sacc[1][2*kc+1][1], v01, v11);
            }
        }

        __syncthreads();
    }

    // ---- epilogue (unpack f16 O to f32 here; loop regs dead) ----
    float* Of = (float*)(sm);
    float* ls = (float*)(sm + 33792u);

    if (r4 == 0) {
        ls[ch * 128 + base_r + gg]      = lacc[0][0];
        ls[ch * 128 + base_r + gg + 8]  = lacc[0][2];
        ls[ch * 128 + base_r + gg + 16] = lacc[1][0];
        ls[ch * 128 + base_r + gg + 24] = lacc[1][2];
    }
    if (ch == 1) {
        #pragma unroll
        for (int m = 0; m < 2; m++)
            #pragma unroll
            for (int nb = 0; nb < 8; nb++) {
                int ra = base_r + 16 * m + gg;
                float2 f0 = __half22float2(*(__half2*)&oacc[m][nb][0]);
                float2 f1 = __half22float2(*(__half2*)&oacc[m][nb][1]);
                *(float2*)&Of[ra * 66 + 8 * nb + 2 * r4]       = f0;
                *(float2*)&Of[(ra + 8) * 66 + 8 * nb + 2 * r4] = f1;
            }
    }
    __syncthreads();

    const int pid = b * 32 + qb;
    if (ch == 0) {
        #pragma unroll
        for (int m = 0; m < 2; m++) {
            int ra = base_r + 16 * m + gg;
            int rb = ra + 8;
            float la = ls[ra] + ls[128 + ra];
            float lb = ls[rb] + ls[128 + rb];
            if (!split) {
                float ia = 1.0f / la, ib = 1.0f / lb;
                #pragma unroll
                for (int nb = 0; nb < 8; nb++) {
                    int col = 8 * nb + 2 * r4;
                    float2 f0 = __half22float2(*(__half2*)&oacc[m][nb][0]);
                    float2 f1 = __half22float2(*(__half2*)&oacc[m][nb][1]);
                    float2 oa = *(float2*)&Of[ra * 66 + col];
                    float2 ob = *(float2*)&Of[rb * 66 + col];
                    float2 va = make_float2((f0.x + oa.x) * ia, (f0.y + oa.y) * ia);
                    float2 vb = make_float2((f1.x + ob.x) * ib, (f1.y + ob.y) * ib);
                    size_t ga  = ((size_t)b * SEQ + (size_t)qb * 128 + ra) * HD + col;
                    size_t gb2 = ((size_t)b * SEQ + (size_t)qb * 128 + rb) * HD + col;
                    *(float2*)&out[ga]  = va;
                    *(float2*)&out[gb2] = vb;
                }
            } else {
                int pra = pid * 128 + ra;
                int prb = pra + 8;
                #pragma unroll
                for (int nb = 0; nb < 8; nb++) {
                    int col = 8 * nb + 2 * r4;
                    float2 f0 = __half22float2(*(__half2*)&oacc[m][nb][0]);
                    float2 f1 = __half22float2(*(__half2*)&oacc[m][nb][1]);
                    float2 oa = *(float2*)&Of[ra * 66 + col];
                    float2 ob = *(float2*)&Of[rb * 66 + col];
                    float2 va = make_float2(f0.x + oa.x, f0.y + oa.y);
                    float2 vb = make_float2(f1.x + ob.x, f1.y + ob.y);
                    *(float2*)&g_opart[((size_t)s * QROWS + pra) * 64 + col] = va;
                    *(float2*)&g_opart[((size_t)s * QROWS + prb) * 64 + col] = vb;
                }
                if (r4 == 0) {
                    g_lpart[s * QROWS + pra] = la;
                    g_lpart[s * QROWS + prb] = lb;
                }
            }
        }
    }

    // ---- in-kernel merge: last of the deg pieces merges ----
    if (split) {
        __threadfence();
        __syncthreads();
        if (tid == 0) s_old = atomicAdd(&g_flag[pid], 1);
        __syncthreads();
        if (s_old == deg - 1) {
            __threadfence();
            int prow0 = pid * 128;
            #pragma unroll
            for (int it = 0; it < 8; it++) {
                int idx = tid + it * 256;
                int rr  = idx >> 4;
                int c4 = (idx & 15) * 4;
                int pr = prow0 + rr;
                float l = 0.f;
                float4 o = make_float4(0.f, 0.f, 0.f, 0.f);
                for (int u = 0; u < deg; u++) {
                    l += g_lpart[u * QROWS + pr];
                    float4 a = *(const float4*)&g_opart[((size_t)u * QROWS + pr) * 64 + c4];
                    o.x += a.x; o.y += a.y; o.z += a.z; o.w += a.w;
                }
                float inv = 1.0f / l;
                o.x *= inv; o.y *= inv; o.z *= inv; o.w *= inv;
                *(float4*)&out[((size_t)b * SEQ + (size_t)qb * 128 + rr) * HD + c4] = o;
            }
            if (tid == 0) g_flag[pid] = 0;
        }
    }
}

// ---------------- launch -----------------------------------------------------
extern "C" void kernel_launch(void* const* d_in, const int* in_sizes, int n_in,
                              void* d_out, int out_size)
{
    const float* x  = (const float*)d_in[0];
    const float* Wk = (const float*)d_in[1];
    const float* Wq = (const float*)d_in[2];
    const float* Wv = (const float*)d_in[3];
    float* out = (float*)d_out;

    cudaFuncSetAttribute(proj_gemm, cudaFuncAttributeMaxDynamicSharedMemorySize,
                         (int)GEMM_SMEM);
    proj_gemm<<<128, 256, GEMM_SMEM>>>(x, Wk, Wq, Wv);

    cudaFuncSetAttribute(attn_kernel, cudaFuncAttributeMaxDynamicSharedMemorySize,
                         (int)ATT_SMEM);
    attn_kernel<<<320, 256, ATT_SMEM>>>(out);
}